// round 2
// baseline (speedup 1.0000x reference)
#include <cuda_runtime.h>
#include <math.h>

// ---------------- problem constants ----------------
#define DIMC 1024
#define NHEADS 16
#define HEAD_DIM 64
#define ROT_DIM 32
#define PB 2
#define PT 32
#define PH 18
#define PW 32
#define NTOK (PB*PT*PH*PW)     // 36864 tokens
#define NSEQ (PB*PH*PW)        // 1152 sequences (b,h,w)
#define E3   (3*DIMC)          // 3072
#define SEQ_STRIDE (PH*PW)     // 576 tokens between consecutive t

// ---------------- scratch (device globals; no allocs allowed) ----------------
__device__ float g_qkv[(size_t)NTOK * E3];     // [token, 3072]
__device__ float g_attn[(size_t)NTOK * DIMC];  // [token, 1024]

// ---------------- fp32 NT SGEMM: C[m,n] = sum_k A[m,k]*B[n,k] (+bias[n]) ----
// A: [M,K] row-major, B: [N,K] row-major, K % 16 == 0, M,N % 128 == 0
#define BM 128
#define BN 128
#define BK 16
#define TM 8
#define TN 8

__global__ __launch_bounds__(256)
void sgemm_nt_kernel(const float* __restrict__ A,
                     const float* __restrict__ B,
                     const float* __restrict__ bias,
                     float* __restrict__ C,
                     int M, int N, int K)
{
    __shared__ float As[BK][BM];
    __shared__ float Bs[BK][BN];

    const int bx = blockIdx.x;   // N tile
    const int by = blockIdx.y;   // M tile
    const int tid = threadIdx.x;

    const int tx = tid % (BN / TN);   // 0..15
    const int ty = tid / (BN / TN);   // 0..15

    const float* Ab = A + (size_t)by * BM * K;
    const float* Bb = B + (size_t)bx * BN * K;

    float acc[TM][TN];
    #pragma unroll
    for (int i = 0; i < TM; i++)
        #pragma unroll
        for (int j = 0; j < TN; j++) acc[i][j] = 0.0f;

    const int lrow = tid >> 2;         // 0..63
    const int lcol = (tid & 3) * 4;    // 0,4,8,12

    for (int k0 = 0; k0 < K; k0 += BK) {
        #pragma unroll
        for (int i = 0; i < 2; i++) {
            int r = lrow + i * 64;
            float4 v = *(const float4*)(Ab + (size_t)r * K + k0 + lcol);
            As[lcol + 0][r] = v.x;
            As[lcol + 1][r] = v.y;
            As[lcol + 2][r] = v.z;
            As[lcol + 3][r] = v.w;
        }
        #pragma unroll
        for (int i = 0; i < 2; i++) {
            int r = lrow + i * 64;
            float4 v = *(const float4*)(Bb + (size_t)r * K + k0 + lcol);
            Bs[lcol + 0][r] = v.x;
            Bs[lcol + 1][r] = v.y;
            Bs[lcol + 2][r] = v.z;
            Bs[lcol + 3][r] = v.w;
        }
        __syncthreads();

        #pragma unroll
        for (int k = 0; k < BK; k++) {
            float am[TM], bn[TN];
            #pragma unroll
            for (int i = 0; i < TM; i++) am[i] = As[k][ty * TM + i];
            #pragma unroll
            for (int j = 0; j < TN; j++) bn[j] = Bs[k][tx * TN + j];
            #pragma unroll
            for (int i = 0; i < TM; i++)
                #pragma unroll
                for (int j = 0; j < TN; j++)
                    acc[i][j] += am[i] * bn[j];
        }
        __syncthreads();
    }

    #pragma unroll
    for (int i = 0; i < TM; i++) {
        size_t row = (size_t)by * BM + ty * TM + i;
        float* Crow = C + row * N + bx * BN + tx * TN;
        int col = bx * BN + tx * TN;
        #pragma unroll
        for (int j = 0; j < TN; j += 4) {
            float4 o;
            if (bias) {
                float4 bv = *(const float4*)(bias + col + j);
                o.x = acc[i][j + 0] + bv.x;
                o.y = acc[i][j + 1] + bv.y;
                o.z = acc[i][j + 2] + bv.z;
                o.w = acc[i][j + 3] + bv.w;
            } else {
                o.x = acc[i][j + 0];
                o.y = acc[i][j + 1];
                o.z = acc[i][j + 2];
                o.w = acc[i][j + 3];
            }
            *(float4*)(Crow + j) = o;
        }
    }
}

// ---------------- fused RoPE + causal attention ----------------
// one block (128 thr) per (seq, head); seq = (b*PH + h)*PW + w; T=32, D=64
__global__ __launch_bounds__(128)
void attn_kernel(const float* __restrict__ qkv, float* __restrict__ outb)
{
    __shared__ float qs[PT][HEAD_DIM];
    __shared__ float ks[PT][HEAD_DIM];
    __shared__ float vs[PT][HEAD_DIM];
    __shared__ float sc[PT][PT + 1];
    __shared__ float freq[ROT_DIM / 2];

    const int tid  = threadIdx.x;
    const int bid  = blockIdx.x;
    const int head = bid & (NHEADS - 1);
    const int seq  = bid >> 4;               // 0..1151
    const int b    = seq / (PH * PW);
    const int hw   = seq - b * (PH * PW);
    const size_t base_tok = (size_t)b * (PT * PH * PW) + hw;  // token at t=0

    if (tid < ROT_DIM / 2) {
        // freq[j] = 10000^(-(2j)/ROT_DIM)
        freq[tid] = __powf(10000.0f, -(float)(2 * tid) / (float)ROT_DIM);
    }

    // cooperative load of q,k,v (each 32x64 floats = 512 float4)
    #pragma unroll
    for (int i = 0; i < 4; i++) {
        int idx = tid + 128 * i;           // 0..511
        int t  = idx >> 4;                 // /16
        int d4 = idx & 15;                 // 16 float4 per row
        const float* base = qkv + (base_tok + (size_t)t * SEQ_STRIDE) * E3
                          + head * HEAD_DIM + d4 * 4;
        *(float4*)&qs[t][d4 * 4] = *(const float4*)(base);
        *(float4*)&ks[t][d4 * 4] = *(const float4*)(base + DIMC);
        *(float4*)&vs[t][d4 * 4] = *(const float4*)(base + 2 * DIMC);
    }
    __syncthreads();

    // RoPE on q and k (first 32 dims): 2 tensors * 32 t * 16 pairs = 1024 tasks
    #pragma unroll
    for (int i = 0; i < 8; i++) {
        int task  = tid + 128 * i;
        int which = task >> 9;          // 0: q, 1: k
        int rem   = task & 511;
        int t     = rem >> 4;
        int j     = rem & 15;
        float ang = (float)t * freq[j];
        float c, s;
        __sincosf(ang, &s, &c);
        float* buf = which ? &ks[t][0] : &qs[t][0];
        float x0 = buf[2 * j], x1 = buf[2 * j + 1];
        buf[2 * j]     = x0 * c - x1 * s;
        buf[2 * j + 1] = x1 * c + x0 * s;
    }
    __syncthreads();

    // scores: each thread computes a 2x4 tile of the 32x32 score matrix
    {
        const int tq0 = (tid >> 3) * 2;     // 0,2,...,30
        const int tk0 = (tid & 7) * 4;      // 0,4,...,28
        float a2[2][4];
        #pragma unroll
        for (int i = 0; i < 2; i++)
            #pragma unroll
            for (int j = 0; j < 4; j++) a2[i][j] = 0.0f;

        #pragma unroll
        for (int d = 0; d < HEAD_DIM; d += 4) {
            float4 q0 = *(float4*)&qs[tq0][d];
            float4 q1 = *(float4*)&qs[tq0 + 1][d];
            #pragma unroll
            for (int j = 0; j < 4; j++) {
                float4 kv = *(float4*)&ks[tk0 + j][d];
                a2[0][j] += q0.x * kv.x + q0.y * kv.y + q0.z * kv.z + q0.w * kv.w;
                a2[1][j] += q1.x * kv.x + q1.y * kv.y + q1.z * kv.z + q1.w * kv.w;
            }
        }
        const float scale = 0.125f;  // 1/sqrt(64)
        #pragma unroll
        for (int i = 0; i < 2; i++)
            #pragma unroll
            for (int j = 0; j < 4; j++) {
                int tq = tq0 + i, tk = tk0 + j;
                sc[tq][tk] = (tk <= tq) ? a2[i][j] * scale : -1e30f;
            }
    }
    __syncthreads();

    // softmax: 4 threads per row, 8 cols each, shfl reduce within group of 4
    {
        const int row = tid >> 2;
        const int sub = tid & 3;
        float e[8];
        float m = -1e30f;
        #pragma unroll
        for (int j = 0; j < 8; j++) m = fmaxf(m, sc[row][sub * 8 + j]);
        m = fmaxf(m, __shfl_xor_sync(0xffffffffu, m, 1));
        m = fmaxf(m, __shfl_xor_sync(0xffffffffu, m, 2));
        float sum = 0.0f;
        #pragma unroll
        for (int j = 0; j < 8; j++) {
            e[j] = __expf(sc[row][sub * 8 + j] - m);
            sum += e[j];
        }
        sum += __shfl_xor_sync(0xffffffffu, sum, 1);
        sum += __shfl_xor_sync(0xffffffffu, sum, 2);
        float inv = 1.0f / sum;
        #pragma unroll
        for (int j = 0; j < 8; j++) sc[row][sub * 8 + j] = e[j] * inv;
    }
    __syncthreads();

    // output: each thread computes 2 rows x 8 dims of o = P @ V
    {
        const int tq0 = (tid >> 3) * 2;
        const int d0  = (tid & 7) * 8;
        float o0[8], o1[8];
        #pragma unroll
        for (int j = 0; j < 8; j++) { o0[j] = 0.0f; o1[j] = 0.0f; }

        #pragma unroll
        for (int j = 0; j < PT; j++) {
            float p0 = sc[tq0][j];
            float p1 = sc[tq0 + 1][j];
            float4 va = *(float4*)&vs[j][d0];
            float4 vb = *(float4*)&vs[j][d0 + 4];
            o0[0] += p0 * va.x; o0[1] += p0 * va.y; o0[2] += p0 * va.z; o0[3] += p0 * va.w;
            o0[4] += p0 * vb.x; o0[5] += p0 * vb.y; o0[6] += p0 * vb.z; o0[7] += p0 * vb.w;
            o1[0] += p1 * va.x; o1[1] += p1 * va.y; o1[2] += p1 * va.z; o1[3] += p1 * va.w;
            o1[4] += p1 * vb.x; o1[5] += p1 * vb.y; o1[6] += p1 * vb.z; o1[7] += p1 * vb.w;
        }
        size_t tok0 = base_tok + (size_t)tq0 * SEQ_STRIDE;
        size_t tok1 = tok0 + SEQ_STRIDE;
        float* p0 = outb + tok0 * DIMC + head * HEAD_DIM + d0;
        float* p1 = outb + tok1 * DIMC + head * HEAD_DIM + d0;
        *(float4*)(p0 + 0) = make_float4(o0[0], o0[1], o0[2], o0[3]);
        *(float4*)(p0 + 4) = make_float4(o0[4], o0[5], o0[6], o0[7]);
        *(float4*)(p1 + 0) = make_float4(o1[0], o1[1], o1[2], o1[3]);
        *(float4*)(p1 + 4) = make_float4(o1[4], o1[5], o1[6], o1[7]);
    }
}

// ---------------- launch ----------------
extern "C" void kernel_launch(void* const* d_in, const int* in_sizes, int n_in,
                              void* d_out, int out_size)
{
    const float* x     = (const float*)d_in[0];   // [2,32,18,32,1024]
    const float* w_qkv = (const float*)d_in[1];   // [3072,1024]
    const float* w_out = (const float*)d_in[2];   // [1024,1024]
    const float* b_out = (const float*)d_in[3];   // [1024]
    float* out = (float*)d_out;

    float* qkv;  cudaGetSymbolAddress((void**)&qkv,  g_qkv);
    float* attn; cudaGetSymbolAddress((void**)&attn, g_attn);

    // 1) QKV projection: [36864,1024] x [3072,1024]^T -> [36864,3072]
    {
        dim3 grid(E3 / BN, NTOK / BM);
        sgemm_nt_kernel<<<grid, 256>>>(x, w_qkv, nullptr, qkv, NTOK, E3, DIMC);
    }

    // 2) fused RoPE + causal attention per (seq, head)
    {
        attn_kernel<<<NSEQ * NHEADS, 128>>>(qkv, attn);
    }

    // 3) output projection: [36864,1024] x [1024,1024]^T + b -> [36864,1024]
    {
        dim3 grid(DIMC / BN, NTOK / BM);
        sgemm_nt_kernel<<<grid, 256>>>(attn, w_out, b_out, out, NTOK, DIMC, DIMC);
    }
}

// round 5
// speedup vs baseline: 2.6788x; 2.6788x over previous
#include <cuda_runtime.h>
#include <cuda_bf16.h>
#include <cstdint>
#include <math.h>

// ---------------- problem constants ----------------
#define DIMC 1024
#define NHEADS 16
#define HEAD_DIM 64
#define ROT_DIM 32
#define PB 2
#define PT 32
#define PH 18
#define PW 32
#define NTOK (PB*PT*PH*PW)     // 36864 tokens
#define NSEQ (PB*PH*PW)        // 1152 sequences (b,h,w)
#define E3   (3*DIMC)          // 3072
#define SEQ_STRIDE (PH*PW)     // 576 tokens between consecutive t

// ---------------- scratch (device globals; no allocs allowed) ----------------
__device__ float g_qkv[(size_t)NTOK * E3];            // [token, 3072] fp32
__device__ float g_attn[(size_t)NTOK * DIMC];         // [token, 1024] fp32
__device__ __nv_bfloat16 g_xh[(size_t)NTOK * DIMC];
__device__ __nv_bfloat16 g_xl[(size_t)NTOK * DIMC];
__device__ __nv_bfloat16 g_ah[(size_t)NTOK * DIMC];
__device__ __nv_bfloat16 g_al[(size_t)NTOK * DIMC];
__device__ __nv_bfloat16 g_wqh[(size_t)E3 * DIMC];
__device__ __nv_bfloat16 g_wql[(size_t)E3 * DIMC];
__device__ __nv_bfloat16 g_woh[(size_t)DIMC * DIMC];
__device__ __nv_bfloat16 g_wol[(size_t)DIMC * DIMC];

// ---------------- helpers ----------------
__device__ __forceinline__ uint32_t smem_u32(const void* p) {
    uint32_t a;
    asm("{ .reg .u64 t; cvta.to.shared.u64 t, %1; cvt.u32.u64 %0, t; }"
        : "=r"(a) : "l"(p));
    return a;
}

#define CP_ASYNC16(dst, src) \
    asm volatile("cp.async.cg.shared.global [%0], [%1], 16;" :: "r"(dst), "l"(src))
#define CP_COMMIT() asm volatile("cp.async.commit_group;" ::: "memory")
#define CP_WAIT2()  asm volatile("cp.async.wait_group 2;" ::: "memory")
#define CP_WAIT0()  asm volatile("cp.async.wait_group 0;" ::: "memory")

#define LDSM_X4(r0, r1, r2, r3, addr) \
    asm volatile("ldmatrix.sync.aligned.m8n8.x4.shared.b16 {%0,%1,%2,%3}, [%4];" \
        : "=r"(r0), "=r"(r1), "=r"(r2), "=r"(r3) : "r"(addr))

#define MMA_BF16(d, a, b) \
    asm volatile("mma.sync.aligned.m16n8k16.row.col.f32.bf16.bf16.f32 " \
        "{%0,%1,%2,%3}, {%4,%5,%6,%7}, {%8,%9}, {%0,%1,%2,%3};" \
        : "+f"((d)[0]), "+f"((d)[1]), "+f"((d)[2]), "+f"((d)[3]) \
        : "r"((a)[0]), "r"((a)[1]), "r"((a)[2]), "r"((a)[3]), \
          "r"((b)[0]), "r"((b)[1]))

// smem tile: 128 logical rows x 32 bf16 (64B), stored as 64 phys rows x 128B
// with XOR-8 swizzle on 16B chunks -> conflict-free ldmatrix + cp.async.
// (r in [0,128), c = 16B-chunk in [0,4))
__device__ __forceinline__ uint32_t tile_off(int r, int c) {
    int pr = r & 63;
    int c8 = ((r >> 6) << 2) + c;
    return (uint32_t)(pr * 128 + ((c8 ^ (pr & 7)) << 4));
}

// ---------------- fp32 -> (hi, lo) bf16 split ----------------
__global__ __launch_bounds__(256)
void split_bf16_kernel(const float* __restrict__ in,
                       __nv_bfloat16* __restrict__ hi,
                       __nv_bfloat16* __restrict__ lo, int n4)
{
    int i = blockIdx.x * blockDim.x + threadIdx.x;
    if (i >= n4) return;
    float4 v = ((const float4*)in)[i];
    __nv_bfloat16 h0 = __float2bfloat16(v.x);
    __nv_bfloat16 h1 = __float2bfloat16(v.y);
    __nv_bfloat16 h2 = __float2bfloat16(v.z);
    __nv_bfloat16 h3 = __float2bfloat16(v.w);
    __nv_bfloat16 l0 = __float2bfloat16(v.x - __bfloat162float(h0));
    __nv_bfloat16 l1 = __float2bfloat16(v.y - __bfloat162float(h1));
    __nv_bfloat16 l2 = __float2bfloat16(v.z - __bfloat162float(h2));
    __nv_bfloat16 l3 = __float2bfloat16(v.w - __bfloat162float(h3));
    __nv_bfloat162 hA; hA.x = h0; hA.y = h1;
    __nv_bfloat162 hB; hB.x = h2; hB.y = h3;
    __nv_bfloat162 lA; lA.x = l0; lA.y = l1;
    __nv_bfloat162 lB; lB.x = l2; lB.y = l3;
    ((__nv_bfloat162*)hi)[2 * i]     = hA;
    ((__nv_bfloat162*)hi)[2 * i + 1] = hB;
    ((__nv_bfloat162*)lo)[2 * i]     = lA;
    ((__nv_bfloat162*)lo)[2 * i + 1] = lB;
}

// ---------------- bf16-split HMMA GEMM ----------------
// C[m,n] = sum_k A[m,k]*B[n,k] (+bias), C fp32.  A,B given as hi/lo bf16.
// CTA: 128x128, warp: 64x32 (2x4 warp grid), BK=32, 3-stage cp.async pipe.
#define TILE_B   8192          // one 128x32 bf16 tile
#define STAGE_B  (4 * TILE_B)  // Ah, Al, Bh, Bl
#define NSTAGE   3
#define GSMEM    (NSTAGE * STAGE_B)   // 96 KB

__global__ __launch_bounds__(256, 2)
void gemm_bf16split_kernel(const __nv_bfloat16* __restrict__ Ah,
                           const __nv_bfloat16* __restrict__ Al,
                           const __nv_bfloat16* __restrict__ Bh,
                           const __nv_bfloat16* __restrict__ Bl,
                           const float* __restrict__ bias,
                           float* __restrict__ C,
                           int N, int K)
{
    extern __shared__ __align__(128) char smem[];
    const uint32_t sb = smem_u32(smem);
    const int tid  = threadIdx.x;
    const int wid  = tid >> 5;
    const int lane = tid & 31;
    const int warp_m = wid >> 2;      // 0..1  (64 rows each)
    const int warp_n = wid & 3;       // 0..3  (32 cols each)

    const size_t arow0 = (size_t)blockIdx.y * 128;
    const size_t brow0 = (size_t)blockIdx.x * 128;
    const __nv_bfloat16* Agh = Ah + arow0 * K;
    const __nv_bfloat16* Agl = Al + arow0 * K;
    const __nv_bfloat16* Bgh = Bh + brow0 * K;
    const __nv_bfloat16* Bgl = Bl + brow0 * K;

    // per-thread load slots: 2 iterations x (row, chunk)
    const int r0l = tid >> 2;               // rows 0..63
    const int r1l = (tid >> 2) + 64;        // rows 64..127
    const int cl  = tid & 3;                // chunk 0..3

    const int nk = K >> 5;                  // K/32

    auto load_stage = [&](int stage, int chunk) {
        uint32_t stb = sb + stage * STAGE_B;
        const int k0 = chunk * 32;
        #pragma unroll
        for (int it = 0; it < 2; it++) {
            int r = it ? r1l : r0l;
            uint32_t so = tile_off(r, cl);
            size_t go = (size_t)r * K + k0 + cl * 8;
            CP_ASYNC16(stb + 0 * TILE_B + so, Agh + go);
            CP_ASYNC16(stb + 1 * TILE_B + so, Agl + go);
            CP_ASYNC16(stb + 2 * TILE_B + so, Bgh + go);
            CP_ASYNC16(stb + 3 * TILE_B + so, Bgl + go);
        }
    };

    // prologue: fill 3 stages
    #pragma unroll
    for (int p = 0; p < NSTAGE; p++) {
        if (p < nk) load_stage(p, p);
        CP_COMMIT();
    }

    float acc[4][4][4];
    #pragma unroll
    for (int mt = 0; mt < 4; mt++)
        #pragma unroll
        for (int nt = 0; nt < 4; nt++)
            #pragma unroll
            for (int j = 0; j < 4; j++) acc[mt][nt][j] = 0.0f;

    // ldmatrix lane addressing (within a tile)
    const int a_row = (lane & 15);          // + m0
    const int a_c   = (lane >> 4);          // + 2*ks
    const int b_row = (lane & 7) + ((lane >> 4) << 3);   // + n0
    const int b_c   = ((lane >> 3) & 1);    // + 2*ks

    for (int i = 0; i < nk; i++) {
        const int s = i % NSTAGE;
        const uint32_t stb = sb + s * STAGE_B;
        CP_WAIT2();
        __syncthreads();

        #pragma unroll
        for (int ks = 0; ks < 2; ks++) {
            uint32_t A_frag[4][4];   // per m-tile, 4 regs
            uint32_t B_frag[4][2];   // per n-tile, 2 regs

            // ---- pass 1: Al * Bh ----
            #pragma unroll
            for (int mt = 0; mt < 4; mt++) {
                int m0 = warp_m * 64 + mt * 16;
                uint32_t ad = stb + 1 * TILE_B + tile_off(m0 + a_row, 2 * ks + a_c);
                LDSM_X4(A_frag[mt][0], A_frag[mt][1], A_frag[mt][2], A_frag[mt][3], ad);
            }
            #pragma unroll
            for (int nh = 0; nh < 2; nh++) {
                int n0 = warp_n * 32 + nh * 16;
                uint32_t bd = stb + 2 * TILE_B + tile_off(n0 + b_row, 2 * ks + b_c);
                LDSM_X4(B_frag[2*nh][0], B_frag[2*nh][1],
                        B_frag[2*nh+1][0], B_frag[2*nh+1][1], bd);
            }
            #pragma unroll
            for (int mt = 0; mt < 4; mt++)
                #pragma unroll
                for (int nt = 0; nt < 4; nt++)
                    MMA_BF16(acc[mt][nt], A_frag[mt], B_frag[nt]);

            // ---- pass 2: Ah * Bh (reuse B) ----
            #pragma unroll
            for (int mt = 0; mt < 4; mt++) {
                int m0 = warp_m * 64 + mt * 16;
                uint32_t ad = stb + 0 * TILE_B + tile_off(m0 + a_row, 2 * ks + a_c);
                LDSM_X4(A_frag[mt][0], A_frag[mt][1], A_frag[mt][2], A_frag[mt][3], ad);
            }
            #pragma unroll
            for (int mt = 0; mt < 4; mt++)
                #pragma unroll
                for (int nt = 0; nt < 4; nt++)
                    MMA_BF16(acc[mt][nt], A_frag[mt], B_frag[nt]);

            // ---- pass 3: Ah * Bl (reuse A) ----
            #pragma unroll
            for (int nh = 0; nh < 2; nh++) {
                int n0 = warp_n * 32 + nh * 16;
                uint32_t bd = stb + 3 * TILE_B + tile_off(n0 + b_row, 2 * ks + b_c);
                LDSM_X4(B_frag[2*nh][0], B_frag[2*nh][1],
                        B_frag[2*nh+1][0], B_frag[2*nh+1][1], bd);
            }
            #pragma unroll
            for (int mt = 0; mt < 4; mt++)
                #pragma unroll
                for (int nt = 0; nt < 4; nt++)
                    MMA_BF16(acc[mt][nt], A_frag[mt], B_frag[nt]);
        }

        __syncthreads();
        int nx = i + NSTAGE;
        if (nx < nk) load_stage(s, nx);
        CP_COMMIT();
    }
    CP_WAIT0();

    // epilogue
    #pragma unroll
    for (int mt = 0; mt < 4; mt++) {
        #pragma unroll
        for (int nt = 0; nt < 4; nt++) {
            size_t row = arow0 + warp_m * 64 + mt * 16 + (lane >> 2);
            int    col = blockIdx.x * 128 + warp_n * 32 + nt * 8 + (lane & 3) * 2;
            float b0 = 0.f, b1 = 0.f;
            if (bias) { b0 = bias[col]; b1 = bias[col + 1]; }
            float2 v0 = make_float2(acc[mt][nt][0] + b0, acc[mt][nt][1] + b1);
            float2 v1 = make_float2(acc[mt][nt][2] + b0, acc[mt][nt][3] + b1);
            *(float2*)(C + row * (size_t)N + col)       = v0;
            *(float2*)(C + (row + 8) * (size_t)N + col) = v1;
        }
    }
}

// ---------------- fused RoPE + causal attention (unchanged, passing) -------
__global__ __launch_bounds__(128)
void attn_kernel(const float* __restrict__ qkv, float* __restrict__ outb)
{
    __shared__ float qs[PT][HEAD_DIM];
    __shared__ float ks[PT][HEAD_DIM];
    __shared__ float vs[PT][HEAD_DIM];
    __shared__ float sc[PT][PT + 1];
    __shared__ float freq[ROT_DIM / 2];

    const int tid  = threadIdx.x;
    const int bid  = blockIdx.x;
    const int head = bid & (NHEADS - 1);
    const int seq  = bid >> 4;
    const int b    = seq / (PH * PW);
    const int hw   = seq - b * (PH * PW);
    const size_t base_tok = (size_t)b * (PT * PH * PW) + hw;

    if (tid < ROT_DIM / 2) {
        freq[tid] = __powf(10000.0f, -(float)(2 * tid) / (float)ROT_DIM);
    }

    #pragma unroll
    for (int i = 0; i < 4; i++) {
        int idx = tid + 128 * i;
        int t  = idx >> 4;
        int d4 = idx & 15;
        const float* base = qkv + (base_tok + (size_t)t * SEQ_STRIDE) * E3
                          + head * HEAD_DIM + d4 * 4;
        *(float4*)&qs[t][d4 * 4] = *(const float4*)(base);
        *(float4*)&ks[t][d4 * 4] = *(const float4*)(base + DIMC);
        *(float4*)&vs[t][d4 * 4] = *(const float4*)(base + 2 * DIMC);
    }
    __syncthreads();

    #pragma unroll
    for (int i = 0; i < 8; i++) {
        int task  = tid + 128 * i;
        int which = task >> 9;
        int rem   = task & 511;
        int t     = rem >> 4;
        int j     = rem & 15;
        float ang = (float)t * freq[j];
        float c, s;
        __sincosf(ang, &s, &c);
        float* buf = which ? &ks[t][0] : &qs[t][0];
        float x0 = buf[2 * j], x1 = buf[2 * j + 1];
        buf[2 * j]     = x0 * c - x1 * s;
        buf[2 * j + 1] = x1 * c + x0 * s;
    }
    __syncthreads();

    {
        const int tq0 = (tid >> 3) * 2;
        const int tk0 = (tid & 7) * 4;
        float a2[2][4];
        #pragma unroll
        for (int i = 0; i < 2; i++)
            #pragma unroll
            for (int j = 0; j < 4; j++) a2[i][j] = 0.0f;

        #pragma unroll
        for (int d = 0; d < HEAD_DIM; d += 4) {
            float4 q0 = *(float4*)&qs[tq0][d];
            float4 q1 = *(float4*)&qs[tq0 + 1][d];
            #pragma unroll
            for (int j = 0; j < 4; j++) {
                float4 kv = *(float4*)&ks[tk0 + j][d];
                a2[0][j] += q0.x * kv.x + q0.y * kv.y + q0.z * kv.z + q0.w * kv.w;
                a2[1][j] += q1.x * kv.x + q1.y * kv.y + q1.z * kv.z + q1.w * kv.w;
            }
        }
        const float scale = 0.125f;
        #pragma unroll
        for (int i = 0; i < 2; i++)
            #pragma unroll
            for (int j = 0; j < 4; j++) {
                int tq = tq0 + i, tk = tk0 + j;
                sc[tq][tk] = (tk <= tq) ? a2[i][j] * scale : -1e30f;
            }
    }
    __syncthreads();

    {
        const int row = tid >> 2;
        const int sub = tid & 3;
        float e[8];
        float m = -1e30f;
        #pragma unroll
        for (int j = 0; j < 8; j++) m = fmaxf(m, sc[row][sub * 8 + j]);
        m = fmaxf(m, __shfl_xor_sync(0xffffffffu, m, 1));
        m = fmaxf(m, __shfl_xor_sync(0xffffffffu, m, 2));
        float sum = 0.0f;
        #pragma unroll
        for (int j = 0; j < 8; j++) {
            e[j] = __expf(sc[row][sub * 8 + j] - m);
            sum += e[j];
        }
        sum += __shfl_xor_sync(0xffffffffu, sum, 1);
        sum += __shfl_xor_sync(0xffffffffu, sum, 2);
        float inv = 1.0f / sum;
        #pragma unroll
        for (int j = 0; j < 8; j++) sc[row][sub * 8 + j] = e[j] * inv;
    }
    __syncthreads();

    {
        const int tq0 = (tid >> 3) * 2;
        const int d0  = (tid & 7) * 8;
        float o0[8], o1[8];
        #pragma unroll
        for (int j = 0; j < 8; j++) { o0[j] = 0.0f; o1[j] = 0.0f; }

        #pragma unroll
        for (int j = 0; j < PT; j++) {
            float p0 = sc[tq0][j];
            float p1 = sc[tq0 + 1][j];
            float4 va = *(float4*)&vs[j][d0];
            float4 vb = *(float4*)&vs[j][d0 + 4];
            o0[0] += p0 * va.x; o0[1] += p0 * va.y; o0[2] += p0 * va.z; o0[3] += p0 * va.w;
            o0[4] += p0 * vb.x; o0[5] += p0 * vb.y; o0[6] += p0 * vb.z; o0[7] += p0 * vb.w;
            o1[0] += p1 * va.x; o1[1] += p1 * va.y; o1[2] += p1 * va.z; o1[3] += p1 * va.w;
            o1[4] += p1 * vb.x; o1[5] += p1 * vb.y; o1[6] += p1 * vb.z; o1[7] += p1 * vb.w;
        }
        size_t tok0 = base_tok + (size_t)tq0 * SEQ_STRIDE;
        size_t tok1 = tok0 + SEQ_STRIDE;
        float* p0 = outb + tok0 * DIMC + head * HEAD_DIM + d0;
        float* p1 = outb + tok1 * DIMC + head * HEAD_DIM + d0;
        *(float4*)(p0 + 0) = make_float4(o0[0], o0[1], o0[2], o0[3]);
        *(float4*)(p0 + 4) = make_float4(o0[4], o0[5], o0[6], o0[7]);
        *(float4*)(p1 + 0) = make_float4(o1[0], o1[1], o1[2], o1[3]);
        *(float4*)(p1 + 4) = make_float4(o1[4], o1[5], o1[6], o1[7]);
    }
}

// ---------------- launch ----------------
extern "C" void kernel_launch(void* const* d_in, const int* in_sizes, int n_in,
                              void* d_out, int out_size)
{
    const float* x     = (const float*)d_in[0];
    const float* w_qkv = (const float*)d_in[1];
    const float* w_out = (const float*)d_in[2];
    const float* b_out = (const float*)d_in[3];
    float* out = (float*)d_out;

    float* qkv;  cudaGetSymbolAddress((void**)&qkv,  g_qkv);
    float* attn; cudaGetSymbolAddress((void**)&attn, g_attn);
    __nv_bfloat16 *xh, *xl, *ah, *al, *wqh, *wql, *woh, *wol;
    cudaGetSymbolAddress((void**)&xh,  g_xh);
    cudaGetSymbolAddress((void**)&xl,  g_xl);
    cudaGetSymbolAddress((void**)&ah,  g_ah);
    cudaGetSymbolAddress((void**)&al,  g_al);
    cudaGetSymbolAddress((void**)&wqh, g_wqh);
    cudaGetSymbolAddress((void**)&wql, g_wql);
    cudaGetSymbolAddress((void**)&woh, g_woh);
    cudaGetSymbolAddress((void**)&wol, g_wol);

    cudaFuncSetAttribute(gemm_bf16split_kernel,
                         cudaFuncAttributeMaxDynamicSharedMemorySize, GSMEM);

    // split inputs
    {
        int n4 = (NTOK * DIMC) / 4;
        split_bf16_kernel<<<(n4 + 255) / 256, 256>>>(x, xh, xl, n4);
        int w4 = (E3 * DIMC) / 4;
        split_bf16_kernel<<<(w4 + 255) / 256, 256>>>(w_qkv, wqh, wql, w4);
        int o4 = (DIMC * DIMC) / 4;
        split_bf16_kernel<<<(o4 + 255) / 256, 256>>>(w_out, woh, wol, o4);
    }

    // 1) QKV projection: [36864,1024] x [3072,1024]^T -> [36864,3072]
    {
        dim3 grid(E3 / 128, NTOK / 128);
        gemm_bf16split_kernel<<<grid, 256, GSMEM>>>(xh, xl, wqh, wql,
                                                    nullptr, qkv, E3, DIMC);
    }

    // 2) fused RoPE + causal attention
    attn_kernel<<<NSEQ * NHEADS, 128>>>(qkv, attn);

    // split attention output
    {
        int n4 = (NTOK * DIMC) / 4;
        split_bf16_kernel<<<(n4 + 255) / 256, 256>>>(attn, ah, al, n4);
    }

    // 3) output projection: [36864,1024] x [1024,1024]^T + b -> [36864,1024]
    {
        dim3 grid(DIMC / 128, NTOK / 128);
        gemm_bf16split_kernel<<<grid, 256, GSMEM>>>(ah, al, woh, wol,
                                                    b_out, out, DIMC, DIMC);
    }
}

// round 10
// speedup vs baseline: 3.4941x; 1.3044x over previous
#include <cuda_runtime.h>
#include <cuda_bf16.h>
#include <cuda_fp16.h>
#include <cstdint>
#include <math.h>

// ---------------- problem constants ----------------
#define DIMC 1024
#define NHEADS 16
#define HEAD_DIM 64
#define ROT_DIM 32
#define PB 2
#define PT 32
#define PH 18
#define PW 32
#define NTOK (PB*PT*PH*PW)     // 36864 tokens
#define NSEQ (PB*PH*PW)        // 1152 sequences (b,h,w)
#define E3   (3*DIMC)          // 3072
#define SEQ_STRIDE (PH*PW)     // 576 tokens between consecutive t

// ---------------- scratch (device globals; no allocs allowed) ----------------
__device__ float  g_qkv[(size_t)NTOK * E3];        // [token, 3072] fp32
__device__ __half g_xh[(size_t)NTOK * DIMC];       // x split hi (fp16)
__device__ __half g_xl[(size_t)NTOK * DIMC];       // x split lo (fp16)
__device__ __half g_ah[(size_t)NTOK * DIMC];       // attn-out split hi
__device__ __half g_al[(size_t)NTOK * DIMC];       // attn-out split lo
__device__ __half g_wqh[(size_t)E3 * DIMC];        // w_qkv fp16
__device__ __half g_woh[(size_t)DIMC * DIMC];      // w_out fp16

// ---------------- helpers ----------------
__device__ __forceinline__ uint32_t smem_u32(const void* p) {
    uint32_t a;
    asm("{ .reg .u64 t; cvta.to.shared.u64 t, %1; cvt.u32.u64 %0, t; }"
        : "=r"(a) : "l"(p));
    return a;
}

#define CP_ASYNC16(dst, src) \
    asm volatile("cp.async.cg.shared.global [%0], [%1], 16;" :: "r"(dst), "l"(src))
#define CP_COMMIT() asm volatile("cp.async.commit_group;" ::: "memory")
#define CP_WAIT3()  asm volatile("cp.async.wait_group 3;" ::: "memory")
#define CP_WAIT0()  asm volatile("cp.async.wait_group 0;" ::: "memory")

#define LDSM_X4(r0, r1, r2, r3, addr) \
    asm volatile("ldmatrix.sync.aligned.m8n8.x4.shared.b16 {%0,%1,%2,%3}, [%4];" \
        : "=r"(r0), "=r"(r1), "=r"(r2), "=r"(r3) : "r"(addr))

#define MMA_FP16(d, a, b) \
    asm volatile("mma.sync.aligned.m16n8k16.row.col.f32.f16.f16.f32 " \
        "{%0,%1,%2,%3}, {%4,%5,%6,%7}, {%8,%9}, {%0,%1,%2,%3};" \
        : "+f"((d)[0]), "+f"((d)[1]), "+f"((d)[2]), "+f"((d)[3]) \
        : "r"((a)[0]), "r"((a)[1]), "r"((a)[2]), "r"((a)[3]), \
          "r"((b)[0]), "r"((b)[1]))

// smem tile: 128 logical rows x 32 fp16 (64B), stored as 64 phys rows x 128B
// with XOR-8 swizzle on 16B chunks -> conflict-free ldmatrix + cp.async.
__device__ __forceinline__ uint32_t tile_off(int r, int c) {
    int pr = r & 63;
    int c8 = ((r >> 6) << 2) + c;
    return (uint32_t)(pr * 128 + ((c8 ^ (pr & 7)) << 4));
}

// ---------------- fp32 -> (hi, lo) fp16 split ----------------
__global__ __launch_bounds__(256)
void split_fp16_kernel(const float* __restrict__ in,
                       __half* __restrict__ hi,
                       __half* __restrict__ lo, int n4)
{
    int i = blockIdx.x * blockDim.x + threadIdx.x;
    if (i >= n4) return;
    float4 v = ((const float4*)in)[i];
    __half h0 = __float2half(v.x);
    __half h1 = __float2half(v.y);
    __half h2 = __float2half(v.z);
    __half h3 = __float2half(v.w);
    __half l0 = __float2half(v.x - __half2float(h0));
    __half l1 = __float2half(v.y - __half2float(h1));
    __half l2 = __float2half(v.z - __half2float(h2));
    __half l3 = __float2half(v.w - __half2float(h3));
    __half2 hA = __halves2half2(h0, h1), hB = __halves2half2(h2, h3);
    __half2 lA = __halves2half2(l0, l1), lB = __halves2half2(l2, l3);
    ((__half2*)hi)[2 * i]     = hA;
    ((__half2*)hi)[2 * i + 1] = hB;
    ((__half2*)lo)[2 * i]     = lA;
    ((__half2*)lo)[2 * i + 1] = lB;
}

// ---------------- fp32 -> fp16 round ----------------
__global__ __launch_bounds__(256)
void round_fp16_kernel(const float* __restrict__ in,
                       __half* __restrict__ out, int n4)
{
    int i = blockIdx.x * blockDim.x + threadIdx.x;
    if (i >= n4) return;
    float4 v = ((const float4*)in)[i];
    __half2 a = __halves2half2(__float2half(v.x), __float2half(v.y));
    __half2 b = __halves2half2(__float2half(v.z), __float2half(v.w));
    ((__half2*)out)[2 * i]     = a;
    ((__half2*)out)[2 * i + 1] = b;
}

// ---------------- fp16 2-pass HMMA GEMM ----------------
// C[m,n] = sum_k A[m,k]*B[n,k] (+bias), A = Ah+Al (fp16 split), B = Bh (fp16).
// CTA: 128x128, warp: 64x32 (2x4), BK=32, 4-stage cp.async pipe (96 KB smem).
#define TILE_B   8192          // one 128x32 fp16 tile
#define STAGE_B  (3 * TILE_B)  // Ah, Al, Bh
#define NSTAGE   4
#define GSMEM    (NSTAGE * STAGE_B)   // 96 KB

__global__ __launch_bounds__(256, 2)
void gemm_fp16split_kernel(const __half* __restrict__ Ah,
                           const __half* __restrict__ Al,
                           const __half* __restrict__ Bh,
                           const float* __restrict__ bias,
                           float* __restrict__ C,
                           int N, int K)
{
    extern __shared__ __align__(128) char smem[];
    const uint32_t sb = smem_u32(smem);
    const int tid  = threadIdx.x;
    const int wid  = tid >> 5;
    const int lane = tid & 31;
    const int warp_m = wid >> 2;      // 0..1  (64 rows each)
    const int warp_n = wid & 3;       // 0..3  (32 cols each)

    const size_t arow0 = (size_t)blockIdx.y * 128;
    const size_t brow0 = (size_t)blockIdx.x * 128;
    const __half* Agh = Ah + arow0 * K;
    const __half* Agl = Al + arow0 * K;
    const __half* Bgh = Bh + brow0 * K;

    const int r0l = tid >> 2;               // rows 0..63
    const int r1l = (tid >> 2) + 64;        // rows 64..127
    const int cl  = tid & 3;                // chunk 0..3

    const int nk = K >> 5;                  // K/32

    auto load_stage = [&](int stage, int chunk) {
        uint32_t stb = sb + stage * STAGE_B;
        const int k0 = chunk * 32;
        #pragma unroll
        for (int it = 0; it < 2; it++) {
            int r = it ? r1l : r0l;
            uint32_t so = tile_off(r, cl);
            size_t go = (size_t)r * K + k0 + cl * 8;
            CP_ASYNC16(stb + 0 * TILE_B + so, Agh + go);
            CP_ASYNC16(stb + 1 * TILE_B + so, Agl + go);
            CP_ASYNC16(stb + 2 * TILE_B + so, Bgh + go);
        }
    };

    // prologue: fill stages
    #pragma unroll
    for (int p = 0; p < NSTAGE; p++) {
        if (p < nk) load_stage(p, p);
        CP_COMMIT();
    }

    float acc[4][4][4];
    #pragma unroll
    for (int mt = 0; mt < 4; mt++)
        #pragma unroll
        for (int nt = 0; nt < 4; nt++)
            #pragma unroll
            for (int j = 0; j < 4; j++) acc[mt][nt][j] = 0.0f;

    const int a_row = (lane & 15);
    const int a_c   = (lane >> 4);
    const int b_row = (lane & 7) + ((lane >> 4) << 3);
    const int b_c   = ((lane >> 3) & 1);

    for (int i = 0; i < nk; i++) {
        const int s = i % NSTAGE;
        const uint32_t stb = sb + s * STAGE_B;
        CP_WAIT3();
        __syncthreads();

        #pragma unroll
        for (int ks = 0; ks < 2; ks++) {
            uint32_t A_frag[4][4];
            uint32_t B_frag[4][2];

            // B loaded once, reused across both A passes
            #pragma unroll
            for (int nh = 0; nh < 2; nh++) {
                int n0 = warp_n * 32 + nh * 16;
                uint32_t bd = stb + 2 * TILE_B + tile_off(n0 + b_row, 2 * ks + b_c);
                LDSM_X4(B_frag[2*nh][0], B_frag[2*nh][1],
                        B_frag[2*nh+1][0], B_frag[2*nh+1][1], bd);
            }

            // pass 1: Al * Bh
            #pragma unroll
            for (int mt = 0; mt < 4; mt++) {
                int m0 = warp_m * 64 + mt * 16;
                uint32_t ad = stb + 1 * TILE_B + tile_off(m0 + a_row, 2 * ks + a_c);
                LDSM_X4(A_frag[mt][0], A_frag[mt][1], A_frag[mt][2], A_frag[mt][3], ad);
            }
            #pragma unroll
            for (int mt = 0; mt < 4; mt++)
                #pragma unroll
                for (int nt = 0; nt < 4; nt++)
                    MMA_FP16(acc[mt][nt], A_frag[mt], B_frag[nt]);

            // pass 2: Ah * Bh
            #pragma unroll
            for (int mt = 0; mt < 4; mt++) {
                int m0 = warp_m * 64 + mt * 16;
                uint32_t ad = stb + 0 * TILE_B + tile_off(m0 + a_row, 2 * ks + a_c);
                LDSM_X4(A_frag[mt][0], A_frag[mt][1], A_frag[mt][2], A_frag[mt][3], ad);
            }
            #pragma unroll
            for (int mt = 0; mt < 4; mt++)
                #pragma unroll
                for (int nt = 0; nt < 4; nt++)
                    MMA_FP16(acc[mt][nt], A_frag[mt], B_frag[nt]);
        }

        __syncthreads();
        int nx = i + NSTAGE;
        if (nx < nk) load_stage(s, nx);
        CP_COMMIT();
    }
    CP_WAIT0();

    // epilogue
    #pragma unroll
    for (int mt = 0; mt < 4; mt++) {
        #pragma unroll
        for (int nt = 0; nt < 4; nt++) {
            size_t row = arow0 + warp_m * 64 + mt * 16 + (lane >> 2);
            int    col = blockIdx.x * 128 + warp_n * 32 + nt * 8 + (lane & 3) * 2;
            float b0 = 0.f, b1 = 0.f;
            if (bias) { b0 = bias[col]; b1 = bias[col + 1]; }
            float2 v0 = make_float2(acc[mt][nt][0] + b0, acc[mt][nt][1] + b1);
            float2 v1 = make_float2(acc[mt][nt][2] + b0, acc[mt][nt][3] + b1);
            *(float2*)(C + row * (size_t)N + col)       = v0;
            *(float2*)(C + (row + 8) * (size_t)N + col) = v1;
        }
    }
}

// ---------------- fused RoPE + causal attention; epilogue writes fp16 split
__global__ __launch_bounds__(128)
void attn_kernel(const float* __restrict__ qkv,
                 __half* __restrict__ outh, __half* __restrict__ outl)
{
    __shared__ float qs[PT][HEAD_DIM];
    __shared__ float ks[PT][HEAD_DIM];
    __shared__ float vs[PT][HEAD_DIM];
    __shared__ float sc[PT][PT + 1];
    __shared__ float freq[ROT_DIM / 2];

    const int tid  = threadIdx.x;
    const int bid  = blockIdx.x;
    const int head = bid & (NHEADS - 1);
    const int seq  = bid >> 4;
    const int b    = seq / (PH * PW);
    const int hw   = seq - b * (PH * PW);
    const size_t base_tok = (size_t)b * (PT * PH * PW) + hw;

    if (tid < ROT_DIM / 2) {
        freq[tid] = __powf(10000.0f, -(float)(2 * tid) / (float)ROT_DIM);
    }

    #pragma unroll
    for (int i = 0; i < 4; i++) {
        int idx = tid + 128 * i;
        int t  = idx >> 4;
        int d4 = idx & 15;
        const float* base = qkv + (base_tok + (size_t)t * SEQ_STRIDE) * E3
                          + head * HEAD_DIM + d4 * 4;
        *(float4*)&qs[t][d4 * 4] = *(const float4*)(base);
        *(float4*)&ks[t][d4 * 4] = *(const float4*)(base + DIMC);
        *(float4*)&vs[t][d4 * 4] = *(const float4*)(base + 2 * DIMC);
    }
    __syncthreads();

    #pragma unroll
    for (int i = 0; i < 8; i++) {
        int task  = tid + 128 * i;
        int which = task >> 9;
        int rem   = task & 511;
        int t     = rem >> 4;
        int j     = rem & 15;
        float ang = (float)t * freq[j];
        float c, s;
        __sincosf(ang, &s, &c);
        float* buf = which ? &ks[t][0] : &qs[t][0];
        float x0 = buf[2 * j], x1 = buf[2 * j + 1];
        buf[2 * j]     = x0 * c - x1 * s;
        buf[2 * j + 1] = x1 * c + x0 * s;
    }
    __syncthreads();

    {
        const int tq0 = (tid >> 3) * 2;
        const int tk0 = (tid & 7) * 4;
        float a2[2][4];
        #pragma unroll
        for (int i = 0; i < 2; i++)
            #pragma unroll
            for (int j = 0; j < 4; j++) a2[i][j] = 0.0f;

        #pragma unroll
        for (int d = 0; d < HEAD_DIM; d += 4) {
            float4 q0 = *(float4*)&qs[tq0][d];
            float4 q1 = *(float4*)&qs[tq0 + 1][d];
            #pragma unroll
            for (int j = 0; j < 4; j++) {
                float4 kv = *(float4*)&ks[tk0 + j][d];
                a2[0][j] += q0.x * kv.x + q0.y * kv.y + q0.z * kv.z + q0.w * kv.w;
                a2[1][j] += q1.x * kv.x + q1.y * kv.y + q1.z * kv.z + q1.w * kv.w;
            }
        }
        const float scale = 0.125f;
        #pragma unroll
        for (int i = 0; i < 2; i++)
            #pragma unroll
            for (int j = 0; j < 4; j++) {
                int tq = tq0 + i, tk = tk0 + j;
                sc[tq][tk] = (tk <= tq) ? a2[i][j] * scale : -1e30f;
            }
    }
    __syncthreads();

    {
        const int row = tid >> 2;
        const int sub = tid & 3;
        float e[8];
        float m = -1e30f;
        #pragma unroll
        for (int j = 0; j < 8; j++) m = fmaxf(m, sc[row][sub * 8 + j]);
        m = fmaxf(m, __shfl_xor_sync(0xffffffffu, m, 1));
        m = fmaxf(m, __shfl_xor_sync(0xffffffffu, m, 2));
        float sum = 0.0f;
        #pragma unroll
        for (int j = 0; j < 8; j++) {
            e[j] = __expf(sc[row][sub * 8 + j] - m);
            sum += e[j];
        }
        sum += __shfl_xor_sync(0xffffffffu, sum, 1);
        sum += __shfl_xor_sync(0xffffffffu, sum, 2);
        float inv = 1.0f / sum;
        #pragma unroll
        for (int j = 0; j < 8; j++) sc[row][sub * 8 + j] = e[j] * inv;
    }
    __syncthreads();

    {
        const int tq0 = (tid >> 3) * 2;
        const int d0  = (tid & 7) * 8;
        float o0[8], o1[8];
        #pragma unroll
        for (int j = 0; j < 8; j++) { o0[j] = 0.0f; o1[j] = 0.0f; }

        #pragma unroll
        for (int j = 0; j < PT; j++) {
            float p0 = sc[tq0][j];
            float p1 = sc[tq0 + 1][j];
            float4 va = *(float4*)&vs[j][d0];
            float4 vb = *(float4*)&vs[j][d0 + 4];
            o0[0] += p0 * va.x; o0[1] += p0 * va.y; o0[2] += p0 * va.z; o0[3] += p0 * va.w;
            o0[4] += p0 * vb.x; o0[5] += p0 * vb.y; o0[6] += p0 * vb.z; o0[7] += p0 * vb.w;
            o1[0] += p1 * va.x; o1[1] += p1 * va.y; o1[2] += p1 * va.z; o1[3] += p1 * va.w;
            o1[4] += p1 * vb.x; o1[5] += p1 * vb.y; o1[6] += p1 * vb.z; o1[7] += p1 * vb.w;
        }
        size_t tok0 = base_tok + (size_t)tq0 * SEQ_STRIDE;
        size_t tok1 = tok0 + SEQ_STRIDE;
        size_t off0 = tok0 * DIMC + head * HEAD_DIM + d0;
        size_t off1 = tok1 * DIMC + head * HEAD_DIM + d0;

        // fp16 hi/lo split store (8 halves = uint4 each)
        #pragma unroll
        for (int r = 0; r < 2; r++) {
            const float* o = r ? o1 : o0;
            size_t off = r ? off1 : off0;
            __half2 h[4], l[4];
            #pragma unroll
            for (int j = 0; j < 4; j++) {
                __half ha = __float2half(o[2*j]);
                __half hb = __float2half(o[2*j+1]);
                __half la = __float2half(o[2*j]   - __half2float(ha));
                __half lb = __float2half(o[2*j+1] - __half2float(hb));
                h[j] = __halves2half2(ha, hb);
                l[j] = __halves2half2(la, lb);
            }
            *(uint4*)(outh + off) = *(uint4*)h;
            *(uint4*)(outl + off) = *(uint4*)l;
        }
    }
}

// ---------------- launch ----------------
extern "C" void kernel_launch(void* const* d_in, const int* in_sizes, int n_in,
                              void* d_out, int out_size)
{
    const float* x     = (const float*)d_in[0];
    const float* w_qkv = (const float*)d_in[1];
    const float* w_out = (const float*)d_in[2];
    const float* b_out = (const float*)d_in[3];
    float* out = (float*)d_out;

    float* qkv;  cudaGetSymbolAddress((void**)&qkv, g_qkv);
    __half *xh, *xl, *ah, *al, *wqh, *woh;
    cudaGetSymbolAddress((void**)&xh,  g_xh);
    cudaGetSymbolAddress((void**)&xl,  g_xl);
    cudaGetSymbolAddress((void**)&ah,  g_ah);
    cudaGetSymbolAddress((void**)&al,  g_al);
    cudaGetSymbolAddress((void**)&wqh, g_wqh);
    cudaGetSymbolAddress((void**)&woh, g_woh);

    cudaFuncSetAttribute(gemm_fp16split_kernel,
                         cudaFuncAttributeMaxDynamicSharedMemorySize, GSMEM);

    // prepare operands
    {
        int n4 = (NTOK * DIMC) / 4;
        split_fp16_kernel<<<(n4 + 255) / 256, 256>>>(x, xh, xl, n4);
        int w4 = (E3 * DIMC) / 4;
        round_fp16_kernel<<<(w4 + 255) / 256, 256>>>(w_qkv, wqh, w4);
        int o4 = (DIMC * DIMC) / 4;
        round_fp16_kernel<<<(o4 + 255) / 256, 256>>>(w_out, woh, o4);
    }

    // 1) QKV projection: [36864,1024] x [3072,1024]^T -> [36864,3072]
    {
        dim3 grid(E3 / 128, NTOK / 128);
        gemm_fp16split_kernel<<<grid, 256, GSMEM>>>(xh, xl, wqh,
                                                    nullptr, qkv, E3, DIMC);
    }

    // 2) fused RoPE + causal attention (writes fp16 hi/lo directly)
    attn_kernel<<<NSEQ * NHEADS, 128>>>(qkv, ah, al);

    // 3) output projection: [36864,1024] x [1024,1024]^T + b -> [36864,1024]
    {
        dim3 grid(DIMC / 128, NTOK / 128);
        gemm_fp16split_kernel<<<grid, 256, GSMEM>>>(ah, al, woh,
                                                    b_out, out, DIMC, DIMC);
    }
}